// round 14
// baseline (speedup 1.0000x reference)
#include <cuda_runtime.h>
#include <cstdint>
#include <math.h>

// Problem constants
#define B_   64
#define T_   4096
#define D_   512
#define NSEG 32                          // segments per batch
#define SEG_ROWS 128                     // rows per segment
#define NWARP 8
#define THREADS 256
#define TILE_ROWS 16                     // rows per smem tile
#define NTILES (SEG_ROWS / TILE_ROWS)    // 8
#define DEPTH 3                          // smem pipeline stages
#define ROW_BYTES (D_ * 4)               // 2048
#define TILE_BYTES (TILE_ROWS * ROW_BYTES)   // 32768
#define SMEM_DYN (DEPTH * TILE_BYTES)    // 98304

typedef unsigned long long u64;

// Per-(batch,segment) partial online-softmax state + completion counters.
__device__ float g_part_m[B_ * NSEG];
__device__ float g_part_l[B_ * NSEG];
__device__ float g_part_acc[B_ * NSEG * D_];
__device__ int   g_cnt[B_];              // zero-init; self-resetting each launch

__device__ __forceinline__ float neg_inf() { return __int_as_float(0xff800000); }

// ---- packed f32x2 helpers ---------------------------------------------------
__device__ __forceinline__ u64 pack2(float lo, float hi) {
    u64 r; asm("mov.b64 %0,{%1,%2};" : "=l"(r) : "f"(lo), "f"(hi)); return r;
}
__device__ __forceinline__ void unpack2(u64 v, float& lo, float& hi) {
    asm("mov.b64 {%0,%1},%2;" : "=f"(lo), "=f"(hi) : "l"(v));
}
__device__ __forceinline__ u64 fma2(u64 a, u64 b, u64 c) {
    u64 d; asm("fma.rn.f32x2 %0,%1,%2,%3;" : "=l"(d) : "l"(a), "l"(b), "l"(c)); return d;
}
__device__ __forceinline__ u64 mul2(u64 a, u64 b) {
    u64 d; asm("mul.rn.f32x2 %0,%1,%2;" : "=l"(d) : "l"(a), "l"(b)); return d;
}
__device__ __forceinline__ u64 add2(u64 a, u64 b) {
    u64 d; asm("add.rn.f32x2 %0,%1,%2;" : "=l"(d) : "l"(a), "l"(b)); return d;
}

// ---- cp.async (LDGSTS) helpers ----------------------------------------------
__device__ __forceinline__ void cp16(uint32_t dst_smem, const void* src) {
    asm volatile("cp.async.cg.shared.global [%0], [%1], 16;"
                 :: "r"(dst_smem), "l"(src));
}
__device__ __forceinline__ void cp_commit() {
    asm volatile("cp.async.commit_group;");
}
template <int N>
__device__ __forceinline__ void cp_wait() {
    asm volatile("cp.async.wait_group %0;" :: "n"(N));
}

// -----------------------------------------------------------------------------
// cp.async-staged fused kernel. One segment (128 rows) per CTA. Tiles of 16
// rows stream through a 3-deep smem pipeline (64KB/CTA in flight, register-
// free). Each warp computes 2 rows per tile from smem (LDS), keeping its
// online-softmax accumulator in registers. Load depth is decoupled from the
// compute tail — the fix for the ~79% DRAM wall of all register-resident
// variants (R4/R6/R8/R11).
// -----------------------------------------------------------------------------
__global__ __launch_bounds__(THREADS, 2)
void attn_fused(const float* __restrict__ x,
                const float* __restrict__ v,
                float* __restrict__ ctx,     // d_out          [B*D]
                float* __restrict__ wts)     // d_out + B*D    [B*T]
{
    extern __shared__ char smem_raw[];       // DEPTH x 32KB staging
    __shared__ float s_m[NWARP], s_l[NWARP];
    __shared__ float s_scale[NSEG];
    __shared__ int   s_last;

    const int tid  = threadIdx.x;
    const int warp = tid >> 5;
    const int lane = tid & 31;
    const int b    = blockIdx.x / NSEG;
    const int s    = blockIdx.x % NSEG;
    const int t0   = s * SEG_ROWS;

    const char* xb = (const char*)(x + ((size_t)b * T_ + t0) * D_);
    const uint32_t smem_u32 = (uint32_t)__cvta_generic_to_shared(smem_raw);

    // v for this lane's 128 columns, packed as 8 f32x2 (loop-invariant)
    u64 vw[8];
    {
        const ulonglong2* v2 = reinterpret_cast<const ulonglong2*>(v);
        #pragma unroll
        for (int k = 0; k < 4; k++) {
            ulonglong2 t = v2[lane + 32 * k];
            vw[2*k] = t.x; vw[2*k+1] = t.y;
        }
    }

    u64 acc[8];
    #pragma unroll
    for (int i = 0; i < 8; i++) acc[i] = 0ull;   // packed {0.f, 0.f}
    float m = neg_inf();
    float l = 0.f;

    // ---- prologue: issue first DEPTH-1 tiles --------------------------------
    #pragma unroll
    for (int t = 0; t < DEPTH - 1; t++) {
        const char* src = xb + (size_t)t * TILE_BYTES;
        const uint32_t dst = smem_u32 + t * TILE_BYTES;
        #pragma unroll
        for (int j = 0; j < 8; j++) {
            const int off = (tid + j * THREADS) * 16;
            cp16(dst + off, src + off);
        }
        cp_commit();
    }

    // ---- mainloop -----------------------------------------------------------
    #pragma unroll 1
    for (int t = 0; t < NTILES; t++) {
        if (t == NTILES - 1) cp_wait<0>(); else cp_wait<DEPTH - 2>();
        __syncthreads();                  // tile t visible; stage reuse fenced

        // Issue tile t+DEPTH-1 immediately (overlaps with compute below)
        if (t + DEPTH - 1 < NTILES) {
            const int nt = t + DEPTH - 1;
            const char* src = xb + (size_t)nt * TILE_BYTES;
            const uint32_t dst = smem_u32 + (nt % DEPTH) * TILE_BYTES;
            #pragma unroll
            for (int j = 0; j < 8; j++) {
                const int off = (tid + j * THREADS) * 16;
                cp16(dst + off, src + off);
            }
            cp_commit();
        }

        // Compute this warp's 2 rows of tile t from smem
        const char* buf = smem_raw + (t % DEPTH) * TILE_BYTES;
        const ulonglong2* r0p =
            reinterpret_cast<const ulonglong2*>(buf + (2 * warp    ) * ROW_BYTES);
        const ulonglong2* r1p =
            reinterpret_cast<const ulonglong2*>(buf + (2 * warp + 1) * ROW_BYTES);

        u64 xa[8], xc[8];
        #pragma unroll
        for (int k = 0; k < 4; k++) {
            ulonglong2 q0 = r0p[lane + 32 * k];
            xa[2*k] = q0.x; xa[2*k+1] = q0.y;
        }
        #pragma unroll
        for (int k = 0; k < 4; k++) {
            ulonglong2 q1 = r1p[lane + 32 * k];
            xc[2*k] = q1.x; xc[2*k+1] = q1.y;
        }

        u64 ea2 = 0ull, eb2 = 0ull;
        #pragma unroll
        for (int i = 0; i < 8; i++) {
            ea2 = fma2(xa[i], vw[i], ea2);
            eb2 = fma2(xc[i], vw[i], eb2);
        }
        float al, ah, bl, bh;
        unpack2(ea2, al, ah); unpack2(eb2, bl, bh);
        float ea = al + ah, eb = bl + bh;
        #pragma unroll
        for (int o = 16; o; o >>= 1) {    // interleaved butterflies
            ea += __shfl_xor_sync(0xffffffffu, ea, o);
            eb += __shfl_xor_sync(0xffffffffu, eb, o);
        }

        // Raw energies straight to gmem (2 consecutive floats, STG.64)
        if (lane == 0) {
            float2 ev = make_float2(ea, eb);
            *reinterpret_cast<float2*>(wts + (size_t)b * T_ + t0
                                       + t * TILE_ROWS + 2 * warp) = ev;
        }

        const float cmax = fmaxf(ea, eb);
        if (cmax > m) {                   // warp-uniform rescale path
            const float sc = __expf(m - cmax);   // 0 on first tile (m=-inf)
            const u64 sc2 = pack2(sc, sc);
            l *= sc;
            #pragma unroll
            for (int i = 0; i < 8; i++) acc[i] = mul2(acc[i], sc2);
            m = cmax;
        }
        const float pa = __expf(ea - m);
        const float pb = __expf(eb - m);
        const u64 pa2 = pack2(pa, pa);
        const u64 pb2 = pack2(pb, pb);
        l += pa + pb;
        #pragma unroll
        for (int i = 0; i < 8; i++) {
            acc[i] = fma2(xa[i], pa2, acc[i]);
            acc[i] = fma2(xc[i], pb2, acc[i]);
        }
    }

    // ---- in-CTA merge of 8 warp partials (s_acc aliased into staging) -------
    u64* s_acc = reinterpret_cast<u64*>(smem_raw);   // 16KB inside buf[0]

    if (lane == 0) { s_m[warp] = m; s_l[warp] = l; }
    __syncthreads();

    float Mw = neg_inf();
    #pragma unroll
    for (int w = 0; w < NWARP; w++) Mw = fmaxf(Mw, s_m[w]);
    const float wsc = __expf(m - Mw);
    const u64 wsc2 = pack2(wsc, wsc);
    #pragma unroll
    for (int k = 0; k < 4; k++) {
        const int slot = 32 * k + lane;
        s_acc[warp * 256 + slot * 2    ] = mul2(acc[2*k],   wsc2);
        s_acc[warp * 256 + slot * 2 + 1] = mul2(acc[2*k+1], wsc2);
    }
    if (lane == 0) s_l[warp] = l * wsc;
    __syncthreads();

    const int bs = blockIdx.x;
    if (tid < 128) {
        u64 a0 = 0ull, a1 = 0ull;
        #pragma unroll
        for (int w = 0; w < NWARP; w++) {
            a0 = add2(a0, s_acc[w * 256 + tid * 2    ]);
            a1 = add2(a1, s_acc[w * 256 + tid * 2 + 1]);
        }
        ulonglong2 o2; o2.x = a0; o2.y = a1;
        reinterpret_cast<ulonglong2*>(g_part_acc)[(size_t)bs * 128 + tid] = o2;
    }
    if (tid == 0) {
        float L = 0.f;
        #pragma unroll
        for (int w = 0; w < NWARP; w++) L += s_l[w];
        g_part_m[bs] = Mw;
        g_part_l[bs] = L;
    }
    __syncthreads();

    // ---- last-CTA-per-batch detection (threadFenceReduction pattern) --------
    if (tid == 0) {
        __threadfence();
        const int old = atomicAdd(&g_cnt[b], 1);
        s_last = (old == NSEG - 1);
        if (s_last) atomicExch(&g_cnt[b], 0);   // reset for next graph replay
    }
    __syncthreads();
    if (!s_last) return;
    __threadfence();

    // ---- merge 32 segment partials for batch b ------------------------------
    if (tid < NSEG) s_scale[tid] = g_part_m[b * NSEG + tid];  // temp: m_i
    __syncthreads();
    float Mb = neg_inf();
    #pragma unroll
    for (int i = 0; i < NSEG; i++) Mb = fmaxf(Mb, s_scale[i]);
    float Lb = 0.f;
    #pragma unroll
    for (int i = 0; i < NSEG; i++)
        Lb += g_part_l[b * NSEG + i] * __expf(s_scale[i] - Mb);
    const float invL = 1.f / Lb;
    __syncthreads();
    if (tid < NSEG) s_scale[tid] = __expf(s_scale[tid] - Mb) * invL;
    __syncthreads();

    // context[b, :] — 2 columns per thread
    #pragma unroll
    for (int h = 0; h < 2; h++) {
        const int col = tid + h * THREADS;
        float a = 0.f;
        #pragma unroll
        for (int i = 0; i < NSEG; i++)
            a += g_part_acc[(size_t)(b * NSEG + i) * D_ + col] * s_scale[i];
        ctx[(size_t)b * D_ + col] = a;
    }

    // weights[b, :] = exp(e - Mb) * invL   (vectorized in-place)
    {
        float4* wb = reinterpret_cast<float4*>(wts + (size_t)b * T_);
        #pragma unroll
        for (int j = 0; j < 4; j++) {
            float4 w = wb[tid + j * THREADS];
            w.x = __expf(w.x - Mb) * invL;
            w.y = __expf(w.y - Mb) * invL;
            w.z = __expf(w.z - Mb) * invL;
            w.w = __expf(w.w - Mb) * invL;
            wb[tid + j * THREADS] = w;
        }
    }
}

// -----------------------------------------------------------------------------
extern "C" void kernel_launch(void* const* d_in, const int* in_sizes, int n_in,
                              void* d_out, int out_size)
{
    const float* x = (const float*)d_in[0];   // encoder_outputs [B,T,D]
    const float* v = (const float*)d_in[1];   // attn_weights_param [D,1]
    float* out = (float*)d_out;
    float* ctx = out;                 // [B*D]
    float* wts = out + B_ * D_;       // [B*T]

    // Opt in to >48KB dynamic smem (idempotent; not a stream op, capture-safe)
    cudaFuncSetAttribute(attn_fused,
                         cudaFuncAttributeMaxDynamicSharedMemorySize, SMEM_DYN);
    attn_fused<<<B_ * NSEG, THREADS, SMEM_DYN>>>(x, v, ctx, wts);
}

// round 15
// speedup vs baseline: 1.2115x; 1.2115x over previous
#include <cuda_runtime.h>
#include <math.h>

// Problem constants
#define B_   64
#define T_   4096
#define D_   512
#define NSEG 32                         // segments per batch
#define SEG_ROWS (T_ / NSEG)            // 128 rows per segment
#define NWARP 8
#define THREADS 256
#define ROWS_PER_ITER 4
#define NITER (SEG_ROWS / (NWARP * ROWS_PER_ITER))  // 4 iterations

typedef unsigned long long u64;

// Per-(batch,segment) partial online-softmax state + completion counters.
__device__ float g_part_m[B_ * NSEG];
__device__ float g_part_l[B_ * NSEG];
__device__ float g_part_acc[B_ * NSEG * D_];
__device__ int   g_cnt[B_];             // zero-init; self-resetting each launch

__device__ __forceinline__ float neg_inf() { return __int_as_float(0xff800000); }

// ---- packed f32x2 helpers (FFMA2: PTX-only, halves fma-pipe issue) ----------
__device__ __forceinline__ u64 pack2(float lo, float hi) {
    u64 r; asm("mov.b64 %0,{%1,%2};" : "=l"(r) : "f"(lo), "f"(hi)); return r;
}
__device__ __forceinline__ void unpack2(u64 v, float& lo, float& hi) {
    asm("mov.b64 {%0,%1},%2;" : "=f"(lo), "=f"(hi) : "l"(v));
}
__device__ __forceinline__ u64 fma2(u64 a, u64 b, u64 c) {
    u64 d; asm("fma.rn.f32x2 %0,%1,%2,%3;" : "=l"(d) : "l"(a), "l"(b), "l"(c)); return d;
}
__device__ __forceinline__ u64 mul2(u64 a, u64 b) {
    u64 d; asm("mul.rn.f32x2 %0,%1,%2;" : "=l"(d) : "l"(a), "l"(b)); return d;
}
__device__ __forceinline__ u64 add2(u64 a, u64 b) {
    u64 d; asm("add.rn.f32x2 %0,%1,%2;" : "=l"(d) : "l"(a), "l"(b)); return d;
}

// Streaming (evict-first) 16B load: x is read exactly once — don't pollute L2.
__device__ __forceinline__ void ldcs128(const void* p, u64& a, u64& b) {
    asm("ld.global.cs.v2.u64 {%0,%1}, [%2];" : "=l"(a), "=l"(b) : "l"(p));
}

// -----------------------------------------------------------------------------
// Champion kernel (R6) + streaming loads. One segment (128 rows) per CTA,
// 8 warps, each warp runs an independent online softmax over 16 rows, FOUR
// ROWS PER ITERATION (16 front-batched LDG.128.CS = 2KB MLP/warp; 2 CTAs/SM).
// Zero mainloop barriers.
// -----------------------------------------------------------------------------
__global__ __launch_bounds__(THREADS, 2)
void attn_fused(const float* __restrict__ x,
                const float* __restrict__ v,
                float* __restrict__ ctx,     // d_out          [B*D]
                float* __restrict__ wts)     // d_out + B*D    [B*T]
{
    __shared__ float s_e[SEG_ROWS];          // segment energies
    __shared__ float s_m[NWARP], s_l[NWARP];
    __shared__ u64   s_acc[NWARP * 256];     // 16KB cross-warp reduce buffer
    __shared__ float s_scale[NSEG];          // merge-phase segment scales
    __shared__ int   s_last;

    const int tid  = threadIdx.x;
    const int warp = tid >> 5;
    const int lane = tid & 31;
    const int b    = blockIdx.x / NSEG;
    const int s    = blockIdx.x % NSEG;
    const int t0   = s * SEG_ROWS;

    const float* xb = x + ((size_t)b * T_ + t0) * D_;

    // v for this lane's 128 columns, packed as 8 f32x2 (loop-invariant)
    u64 vw[8];
    {
        const ulonglong2* v2 = reinterpret_cast<const ulonglong2*>(v);
        #pragma unroll
        for (int k = 0; k < 4; k++) {
            ulonglong2 t = v2[lane + 32 * k];
            vw[2*k] = t.x; vw[2*k+1] = t.y;
        }
    }

    u64 acc[8];
    #pragma unroll
    for (int i = 0; i < 8; i++) acc[i] = 0ull;   // packed {0.f, 0.f}
    float m = neg_inf();
    float l = 0.f;

    // ---- mainloop: barrier-free per-warp online softmax, 4 rows/iter --------
    #pragma unroll 1
    for (int c = 0; c < NITER; c++) {
        const int r0 = c * (NWARP * ROWS_PER_ITER) + warp * ROWS_PER_ITER;

        // Front-batch 16 independent LDG.128.CS (2KB in flight per warp)
        u64 xd[4][8];
        #pragma unroll
        for (int rr = 0; rr < 4; rr++) {
            const ulonglong2* xr =
                reinterpret_cast<const ulonglong2*>(xb + (size_t)(r0 + rr) * D_);
            #pragma unroll
            for (int k = 0; k < 4; k++) {
                ldcs128(&xr[lane + 32 * k], xd[rr][2*k], xd[rr][2*k+1]);
            }
        }

        // Four independent dot products (packed FMA)
        u64 e2[4];
        #pragma unroll
        for (int rr = 0; rr < 4; rr++) {
            u64 a2 = 0ull;
            #pragma unroll
            for (int i = 0; i < 8; i++) a2 = fma2(xd[rr][i], vw[i], a2);
            e2[rr] = a2;
        }
        float e[4];
        #pragma unroll
        for (int rr = 0; rr < 4; rr++) {
            float lo, hi; unpack2(e2[rr], lo, hi);
            e[rr] = lo + hi;
        }
        // Interleaved butterfly reductions — all four latencies overlap
        #pragma unroll
        for (int o = 16; o; o >>= 1) {
            #pragma unroll
            for (int rr = 0; rr < 4; rr++)
                e[rr] += __shfl_xor_sync(0xffffffffu, e[rr], o);
        }

        if (lane == 0) {
            #pragma unroll
            for (int rr = 0; rr < 4; rr++) s_e[r0 + rr] = e[rr];
        }

        const float cmax = fmaxf(fmaxf(e[0], e[1]), fmaxf(e[2], e[3]));
        if (cmax > m) {                      // warp-uniform rescale path
            const float sc = __expf(m - cmax);   // 0 on first iter (m = -inf)
            const u64 sc2 = pack2(sc, sc);
            l *= sc;
            #pragma unroll
            for (int i = 0; i < 8; i++) acc[i] = mul2(acc[i], sc2);
            m = cmax;
        }
        #pragma unroll
        for (int rr = 0; rr < 4; rr++) {
            const float p = __expf(e[rr] - m);
            const u64 p2 = pack2(p, p);
            l += p;
            #pragma unroll
            for (int i = 0; i < 8; i++)
                acc[i] = fma2(xd[rr][i], p2, acc[i]);
        }
    }

    // ---- in-CTA merge of 8 warp partials ------------------------------------
    if (lane == 0) { s_m[warp] = m; s_l[warp] = l; }
    __syncthreads();

    float Mw = neg_inf();
    #pragma unroll
    for (int w = 0; w < NWARP; w++) Mw = fmaxf(Mw, s_m[w]);
    const float wsc = __expf(m - Mw);
    const u64 wsc2 = pack2(wsc, wsc);
    #pragma unroll
    for (int k = 0; k < 4; k++) {
        const int slot = 32 * k + lane;
        s_acc[warp * 256 + slot * 2    ] = mul2(acc[2*k],   wsc2);
        s_acc[warp * 256 + slot * 2 + 1] = mul2(acc[2*k+1], wsc2);
    }
    if (lane == 0) s_l[warp] = l * wsc;
    __syncthreads();

    const int bs = b * NSEG + s;
    if (tid < 128) {
        u64 a0 = 0ull, a1 = 0ull;
        #pragma unroll
        for (int w = 0; w < NWARP; w++) {
            a0 = add2(a0, s_acc[w * 256 + tid * 2    ]);
            a1 = add2(a1, s_acc[w * 256 + tid * 2 + 1]);
        }
        ulonglong2 o2; o2.x = a0; o2.y = a1;
        reinterpret_cast<ulonglong2*>(g_part_acc)[(size_t)bs * 128 + tid] = o2;
    }
    if (tid < SEG_ROWS) {
        wts[(size_t)b * T_ + t0 + tid] = s_e[tid];   // raw energies (coalesced)
    }
    if (tid == 0) {
        float L = 0.f;
        #pragma unroll
        for (int w = 0; w < NWARP; w++) L += s_l[w];
        g_part_m[bs] = Mw;
        g_part_l[bs] = L;
    }
    __syncthreads();

    // ---- last-CTA-per-batch detection (threadFenceReduction pattern) --------
    if (tid == 0) {
        __threadfence();
        const int old = atomicAdd(&g_cnt[b], 1);
        s_last = (old == NSEG - 1);
        if (s_last) atomicExch(&g_cnt[b], 0);   // reset for next graph replay
    }
    __syncthreads();
    if (!s_last) return;
    __threadfence();

    // ---- merge 32 segment partials for batch b ------------------------------
    if (tid < NSEG) s_scale[tid] = g_part_m[b * NSEG + tid];  // temp: m_i
    __syncthreads();
    float Mb = neg_inf();
    #pragma unroll
    for (int i = 0; i < NSEG; i++) Mb = fmaxf(Mb, s_scale[i]);
    float Lb = 0.f;
    #pragma unroll
    for (int i = 0; i < NSEG; i++)
        Lb += g_part_l[b * NSEG + i] * __expf(s_scale[i] - Mb);
    const float invL = 1.f / Lb;
    __syncthreads();
    if (tid < NSEG) s_scale[tid] = __expf(s_scale[tid] - Mb) * invL;
    __syncthreads();

    // context[b, :] — 2 columns per thread
    #pragma unroll
    for (int h = 0; h < 2; h++) {
        const int col = tid + h * THREADS;
        float a = 0.f;
        #pragma unroll
        for (int i = 0; i < NSEG; i++)
            a += g_part_acc[(size_t)(b * NSEG + i) * D_ + col] * s_scale[i];
        ctx[(size_t)b * D_ + col] = a;
    }

    // weights[b, :] = exp(e - Mb) * invL   (vectorized in-place)
    {
        float4* wb = reinterpret_cast<float4*>(wts + (size_t)b * T_);
        #pragma unroll
        for (int j = 0; j < 4; j++) {
            float4 w = wb[tid + j * THREADS];
            w.x = __expf(w.x - Mb) * invL;
            w.y = __expf(w.y - Mb) * invL;
            w.z = __expf(w.z - Mb) * invL;
            w.w = __expf(w.w - Mb) * invL;
            wb[tid + j * THREADS] = w;
        }
    }
}

// -----------------------------------------------------------------------------
extern "C" void kernel_launch(void* const* d_in, const int* in_sizes, int n_in,
                              void* d_out, int out_size)
{
    const float* x = (const float*)d_in[0];   // encoder_outputs [B,T,D]
    const float* v = (const float*)d_in[1];   // attn_weights_param [D,1]
    float* out = (float*)d_out;
    float* ctx = out;                 // [B*D]
    float* wts = out + B_ * D_;       // [B*T]

    attn_fused<<<B_ * NSEG, THREADS>>>(x, v, ctx, wts);
}

// round 16
// speedup vs baseline: 1.2409x; 1.0242x over previous
#include <cuda_runtime.h>
#include <math.h>

// Problem constants
#define B_   64
#define T_   4096
#define D_   512
#define NSEG 32                         // segments per batch
#define SEG_ROWS (T_ / NSEG)            // 128 rows per segment
#define NWARP 8
#define THREADS 256
#define ROWS_PER_ITER 4
#define NITER (SEG_ROWS / (NWARP * ROWS_PER_ITER))  // 4 iterations

typedef unsigned long long u64;

// Per-(batch,segment) partial online-softmax state + completion counters.
__device__ float g_part_m[B_ * NSEG];
__device__ float g_part_l[B_ * NSEG];
__device__ float g_part_acc[B_ * NSEG * D_];
__device__ int   g_cnt[B_];             // zero-init; self-resetting each launch

__device__ __forceinline__ float neg_inf() { return __int_as_float(0xff800000); }

// ---- packed f32x2 helpers (FFMA2: PTX-only, halves fma-pipe issue) ----------
__device__ __forceinline__ u64 pack2(float lo, float hi) {
    u64 r; asm("mov.b64 %0,{%1,%2};" : "=l"(r) : "f"(lo), "f"(hi)); return r;
}
__device__ __forceinline__ void unpack2(u64 v, float& lo, float& hi) {
    asm("mov.b64 {%0,%1},%2;" : "=f"(lo), "=f"(hi) : "l"(v));
}
__device__ __forceinline__ u64 fma2(u64 a, u64 b, u64 c) {
    u64 d; asm("fma.rn.f32x2 %0,%1,%2,%3;" : "=l"(d) : "l"(a), "l"(b), "l"(c)); return d;
}
__device__ __forceinline__ u64 mul2(u64 a, u64 b) {
    u64 d; asm("mul.rn.f32x2 %0,%1,%2;" : "=l"(d) : "l"(a), "l"(b)); return d;
}
__device__ __forceinline__ u64 add2(u64 a, u64 b) {
    u64 d; asm("add.rn.f32x2 %0,%1,%2;" : "=l"(d) : "l"(a), "l"(b)); return d;
}

// Streaming (evict-first) 16B load: x is read exactly once — don't pollute L2.
__device__ __forceinline__ void ldcs128(const void* p, u64& a, u64& b) {
    asm("ld.global.cs.v2.u64 {%0,%1}, [%2];" : "=l"(a), "=l"(b) : "l"(p));
}

// -----------------------------------------------------------------------------
// Champion kernel (R15) + epilogue trims. One segment (128 rows) per CTA,
// 8 warps, independent per-warp online softmax, 4 rows/iter (16 front-batched
// LDG.128.CS = 2KB MLP/warp; 2 CTAs/SM). Zero mainloop barriers. Energies are
// written straight to gmem from the mainloop (one STG.128 per warp per iter).
// -----------------------------------------------------------------------------
__global__ __launch_bounds__(THREADS, 2)
void attn_fused(const float* __restrict__ x,
                const float* __restrict__ v,
                float* __restrict__ ctx,     // d_out          [B*D]
                float* __restrict__ wts)     // d_out + B*D    [B*T]
{
    __shared__ float s_m[NWARP], s_l[NWARP];
    __shared__ u64   s_acc[NWARP * 256];     // 16KB cross-warp reduce buffer
    __shared__ float s_scale[NSEG];          // merge-phase segment scales
    __shared__ int   s_last;

    const int tid  = threadIdx.x;
    const int warp = tid >> 5;
    const int lane = tid & 31;
    const int b    = blockIdx.x / NSEG;
    const int s    = blockIdx.x % NSEG;
    const int t0   = s * SEG_ROWS;

    const float* xb = x + ((size_t)b * T_ + t0) * D_;

    // v for this lane's 128 columns, packed as 8 f32x2 (loop-invariant)
    u64 vw[8];
    {
        const ulonglong2* v2 = reinterpret_cast<const ulonglong2*>(v);
        #pragma unroll
        for (int k = 0; k < 4; k++) {
            ulonglong2 t = v2[lane + 32 * k];
            vw[2*k] = t.x; vw[2*k+1] = t.y;
        }
    }

    u64 acc[8];
    #pragma unroll
    for (int i = 0; i < 8; i++) acc[i] = 0ull;   // packed {0.f, 0.f}
    float m = neg_inf();
    float l = 0.f;

    // ---- mainloop: barrier-free per-warp online softmax, 4 rows/iter --------
    #pragma unroll 1
    for (int c = 0; c < NITER; c++) {
        const int r0 = c * (NWARP * ROWS_PER_ITER) + warp * ROWS_PER_ITER;

        // Front-batch 16 independent LDG.128.CS (2KB in flight per warp)
        u64 xd[4][8];
        #pragma unroll
        for (int rr = 0; rr < 4; rr++) {
            const ulonglong2* xr =
                reinterpret_cast<const ulonglong2*>(xb + (size_t)(r0 + rr) * D_);
            #pragma unroll
            for (int k = 0; k < 4; k++) {
                ldcs128(&xr[lane + 32 * k], xd[rr][2*k], xd[rr][2*k+1]);
            }
        }

        // Four independent dot products (packed FMA)
        u64 e2[4];
        #pragma unroll
        for (int rr = 0; rr < 4; rr++) {
            u64 a2 = 0ull;
            #pragma unroll
            for (int i = 0; i < 8; i++) a2 = fma2(xd[rr][i], vw[i], a2);
            e2[rr] = a2;
        }
        float e[4];
        #pragma unroll
        for (int rr = 0; rr < 4; rr++) {
            float lo, hi; unpack2(e2[rr], lo, hi);
            e[rr] = lo + hi;
        }
        // Interleaved butterfly reductions — all four latencies overlap
        #pragma unroll
        for (int o = 16; o; o >>= 1) {
            #pragma unroll
            for (int rr = 0; rr < 4; rr++)
                e[rr] += __shfl_xor_sync(0xffffffffu, e[rr], o);
        }

        // Raw energies straight to gmem: rows r0..r0+3 are consecutive.
        if (lane == 0) {
            float4 ev = make_float4(e[0], e[1], e[2], e[3]);
            *reinterpret_cast<float4*>(wts + (size_t)b * T_ + t0 + r0) = ev;
        }

        const float cmax = fmaxf(fmaxf(e[0], e[1]), fmaxf(e[2], e[3]));
        if (cmax > m) {                      // warp-uniform rescale path
            const float sc = __expf(m - cmax);   // 0 on first iter (m = -inf)
            const u64 sc2 = pack2(sc, sc);
            l *= sc;
            #pragma unroll
            for (int i = 0; i < 8; i++) acc[i] = mul2(acc[i], sc2);
            m = cmax;
        }
        #pragma unroll
        for (int rr = 0; rr < 4; rr++) {
            const float p = __expf(e[rr] - m);
            const u64 p2 = pack2(p, p);
            l += p;
            #pragma unroll
            for (int i = 0; i < 8; i++)
                acc[i] = fma2(xd[rr][i], p2, acc[i]);
        }
    }

    // ---- in-CTA merge of 8 warp partials ------------------------------------
    if (lane == 0) { s_m[warp] = m; s_l[warp] = l; }
    __syncthreads();

    float Mw = neg_inf();
    #pragma unroll
    for (int w = 0; w < NWARP; w++) Mw = fmaxf(Mw, s_m[w]);
    const float wsc = __expf(m - Mw);
    const u64 wsc2 = pack2(wsc, wsc);
    #pragma unroll
    for (int k = 0; k < 4; k++) {
        const int slot = 32 * k + lane;
        s_acc[warp * 256 + slot * 2    ] = mul2(acc[2*k],   wsc2);
        s_acc[warp * 256 + slot * 2 + 1] = mul2(acc[2*k+1], wsc2);
    }
    if (lane == 0) s_l[warp] = l * wsc;
    __syncthreads();

    const int bs = b * NSEG + s;
    // All 256 threads: reduce one u64 slot each (no half-idle window)
    {
        u64 a0 = 0ull;
        #pragma unroll
        for (int w = 0; w < NWARP; w++)
            a0 = add2(a0, s_acc[w * 256 + tid]);
        reinterpret_cast<u64*>(g_part_acc)[(size_t)bs * 256 + tid] = a0;
    }
    if (tid == 0) {
        float L = 0.f;
        #pragma unroll
        for (int w = 0; w < NWARP; w++) L += s_l[w];
        g_part_m[bs] = Mw;
        g_part_l[bs] = L;
    }
    __syncthreads();

    // ---- last-CTA-per-batch detection (threadFenceReduction pattern) --------
    if (tid == 0) {
        __threadfence();
        const int old = atomicAdd(&g_cnt[b], 1);
        s_last = (old == NSEG - 1);
        if (s_last) atomicExch(&g_cnt[b], 0);   // reset for next graph replay
    }
    __syncthreads();
    if (!s_last) return;
    __threadfence();

    // ---- merge 32 segment partials for batch b ------------------------------
    if (tid < NSEG) s_scale[tid] = g_part_m[b * NSEG + tid];  // temp: m_i
    __syncthreads();
    float Mb = neg_inf();
    #pragma unroll
    for (int i = 0; i < NSEG; i++) Mb = fmaxf(Mb, s_scale[i]);
    float Lb = 0.f;
    #pragma unroll
    for (int i = 0; i < NSEG; i++)
        Lb += g_part_l[b * NSEG + i] * __expf(s_scale[i] - Mb);
    const float invL = 1.f / Lb;
    __syncthreads();
    if (tid < NSEG) s_scale[tid] = __expf(s_scale[tid] - Mb) * invL;
    __syncthreads();

    // context[b, :] — 2 columns per thread
    #pragma unroll
    for (int h = 0; h < 2; h++) {
        const int col = tid + h * THREADS;
        float a = 0.f;
        #pragma unroll
        for (int i = 0; i < NSEG; i++)
            a += g_part_acc[(size_t)(b * NSEG + i) * D_ + col] * s_scale[i];
        ctx[(size_t)b * D_ + col] = a;
    }

    // weights[b, :] = exp(e - Mb) * invL   (vectorized in-place)
    {
        float4* wb = reinterpret_cast<float4*>(wts + (size_t)b * T_);
        #pragma unroll
        for (int j = 0; j < 4; j++) {
            float4 w = wb[tid + j * THREADS];
            w.x = __expf(w.x - Mb) * invL;
            w.y = __expf(w.y - Mb) * invL;
            w.z = __expf(w.z - Mb) * invL;
            w.w = __expf(w.w - Mb) * invL;
            wb[tid + j * THREADS] = w;
        }
    }
}

// -----------------------------------------------------------------------------
extern "C" void kernel_launch(void* const* d_in, const int* in_sizes, int n_in,
                              void* d_out, int out_size)
{
    const float* x = (const float*)d_in[0];   // encoder_outputs [B,T,D]
    const float* v = (const float*)d_in[1];   // attn_weights_param [D,1]
    float* out = (float*)d_out;
    float* ctx = out;                 // [B*D]
    float* wts = out + B_ * D_;       // [B*T]

    attn_fused<<<B_ * NSEG, THREADS>>>(x, v, ctx, wts);
}